// round 1
// baseline (speedup 1.0000x reference)
#include <cuda_runtime.h>

// Problem: out[b,o] = sigmoid( mean_i( x[b,i]*W[i,o] + bias[i,o] ) )
// (Choquet integral with cardinality measure == arithmetic mean; sort telescopes away.)
//
// B=256, IN=1024, OUT=1024. Inputs: d_in[0]=x [256,1,1024] f32,
// d_in[1]=weight [1024,1024] f32, d_in[2]=bias [1024,1024] f32.
// Output: [256,1024] f32.

#define BATCH   256
#define INDIM   1024
#define OUTDIM  1024
#define NPART   8
#define ROWS_PER_PART (INDIM / NPART)   // 128

// scratch for partial bias column sums (no cudaMalloc allowed)
__device__ float g_bias_part[NPART][OUTDIM];

// ---------------------------------------------------------------------------
// Kernel 1: partial column sums of bias. grid = (OUTDIM/256, NPART), 256 thr.
// Coalesced: thread t reads bias[r*OUTDIM + col].
// ---------------------------------------------------------------------------
__global__ void __launch_bounds__(256) bias_colsum_kernel(const float* __restrict__ bias) {
    const int col = blockIdx.x * 256 + threadIdx.x;
    const int r0  = blockIdx.y * ROWS_PER_PART;
    float s = 0.0f;
    #pragma unroll 8
    for (int r = 0; r < ROWS_PER_PART; ++r)
        s += __ldg(&bias[(r0 + r) * OUTDIM + col]);
    g_bias_part[blockIdx.y][col] = s;
}

// ---------------------------------------------------------------------------
// Kernel 2: GEMM (256x1024x1024) + fused bias-sum + sigmoid epilogue.
// BM=32, BN=64, BK=32, 256 threads, each thread computes 4 rows x 2 cols.
// Register-prefetch of next k-tile's global loads to hide L2/DRAM latency.
// grid = (OUTDIM/BN, BATCH/BM) = (16, 8) = 128 blocks.
// ---------------------------------------------------------------------------
#define BM 32
#define BN 64
#define BK 32
#define TM 4
#define TN 2
#define PADK (BK + 4)   // 36 floats: keeps float4 smem ops 16B-aligned (144%16==0)

__global__ void __launch_bounds__(256) gemm_sigmoid_kernel(
        const float* __restrict__ x,
        const float* __restrict__ w,
        float* __restrict__ out) {
    __shared__ float As[BM][PADK];   // A tile, row-major (broadcast reads in inner loop)
    __shared__ float Bs[BK][BN];     // B tile

    const int tid = threadIdx.x;
    const int m0  = blockIdx.y * BM;
    const int n0  = blockIdx.x * BN;
    const int ty  = tid >> 5;          // warp id 0..7 -> row group (4 rows)
    const int tx  = tid & 31;          // lane -> col group (2 cols)

    // global-load mappings
    const int arow = tid >> 3;          // 0..31
    const int ak   = (tid & 7) << 2;    // 0,4,...,28
    const int brow = tid >> 4;          // 0..15
    const int bn   = (tid & 15) << 2;   // 0,4,...,60

    const float* xg  = x + (m0 + arow) * INDIM + ak;
    const float* wg0 = w + brow * OUTDIM + n0 + bn;           // rows brow, brow+16 of k-tile
    const float* wg1 = wg0 + 16 * OUTDIM;

    float acc[TM][TN];
    #pragma unroll
    for (int r = 0; r < TM; ++r)
        #pragma unroll
        for (int j = 0; j < TN; ++j)
            acc[r][j] = 0.0f;

    // prefetch k-tile 0 into registers
    float4 av  = *(const float4*)(xg);
    float4 bv0 = *(const float4*)(wg0);
    float4 bv1 = *(const float4*)(wg1);

    for (int k0 = 0; k0 < INDIM; k0 += BK) {
        // commit prefetched tile to smem
        *(float4*)&As[arow][ak]      = av;
        *(float4*)&Bs[brow][bn]      = bv0;
        *(float4*)&Bs[brow + 16][bn] = bv1;
        __syncthreads();

        // prefetch next tile while computing this one
        const int k1 = k0 + BK;
        if (k1 < INDIM) {
            av  = *(const float4*)(xg + k1);
            bv0 = *(const float4*)(wg0 + (size_t)k1 * OUTDIM);
            bv1 = *(const float4*)(wg1 + (size_t)k1 * OUTDIM);
        }

        #pragma unroll
        for (int k = 0; k < BK; ++k) {
            const float b0 = Bs[k][tx * TN + 0];
            const float b1 = Bs[k][tx * TN + 1];
            #pragma unroll
            for (int r = 0; r < TM; ++r) {
                const float a = As[ty * TM + r][k];   // warp-broadcast LDS
                acc[r][0] = fmaf(a, b0, acc[r][0]);
                acc[r][1] = fmaf(a, b1, acc[r][1]);
            }
        }
        __syncthreads();
    }

    // epilogue: out = sigmoid((acc + colsum(bias)) / INDIM)
    #pragma unroll
    for (int j = 0; j < TN; ++j) {
        const int col = n0 + tx * TN + j;
        float s = 0.0f;
        #pragma unroll
        for (int p = 0; p < NPART; ++p)
            s += g_bias_part[p][col];
        #pragma unroll
        for (int r = 0; r < TM; ++r) {
            const int row = m0 + ty * TM + r;
            const float t = (acc[r][j] + s) * (1.0f / (float)INDIM);
            out[row * OUTDIM + col] = 1.0f / (1.0f + __expf(-t));
        }
    }
}

// ---------------------------------------------------------------------------
extern "C" void kernel_launch(void* const* d_in, const int* in_sizes, int n_in,
                              void* d_out, int out_size) {
    const float* x    = (const float*)d_in[0];
    const float* wgt  = (const float*)d_in[1];
    const float* bias = (const float*)d_in[2];
    float* out        = (float*)d_out;

    (void)in_sizes; (void)n_in; (void)out_size;

    dim3 g1(OUTDIM / 256, NPART);
    bias_colsum_kernel<<<g1, 256>>>(bias);

    dim3 g2(OUTDIM / BN, BATCH / BM);
    gemm_sigmoid_kernel<<<g2, 256>>>(x, wgt, out);
}

// round 2
// speedup vs baseline: 1.0010x; 1.0010x over previous
#include <cuda_runtime.h>
#include <cuda_bf16.h>
#include <cstdint>

// out[b,o] = sigmoid( mean_i( x[b,i]*W[i,o] + bias[i,o] ) )
// = sigmoid( (GEMM(x,W)[b,o] + colsum(bias)[o]) / 1024 )
// Tensor-core bf16 GEMM (mma.sync m16n8k16), fp32->bf16 fused into smem stores.

#define BATCH   256
#define INDIM   1024
#define OUTDIM  1024
#define NPART   8
#define ROWS_PER_PART (INDIM / NPART)

__device__ float g_bias_part[NPART][OUTDIM];

// ---------------------------------------------------------------------------
// Kernel 1: partial column sums of bias (coalesced).
// ---------------------------------------------------------------------------
__global__ void __launch_bounds__(256) bias_colsum_kernel(const float* __restrict__ bias) {
    const int col = blockIdx.x * 256 + threadIdx.x;
    const int r0  = blockIdx.y * ROWS_PER_PART;
    float s = 0.0f;
    #pragma unroll 8
    for (int r = 0; r < ROWS_PER_PART; ++r)
        s += __ldg(&bias[(r0 + r) * OUTDIM + col]);
    g_bias_part[blockIdx.y][col] = s;
}

// ---------------------------------------------------------------------------
// Kernel 2: bf16 tensor-core GEMM + bias-mean + sigmoid epilogue.
// BM=64, BN=128, BK=32. 256 threads = 8 warps in 2(M) x 4(N); warp tile 32x32.
// ---------------------------------------------------------------------------
#define BM 64
#define BN 128
#define BK 32
#define A_STRIDE 72    // bf16 units -> 144B row stride (144 % 128 == 16: conflict-free ldmatrix)
#define B_STRIDE 136   // bf16 units -> 272B row stride (272 % 128 == 16)
#define A_BUF_BYTES (BM * A_STRIDE * 2)   // 9216
#define B_BUF_BYTES (BK * B_STRIDE * 2)   // 8704
#define NITER (INDIM / BK)                // 32

__device__ __forceinline__ void ldmatrix_x4(uint32_t* r, uint32_t addr) {
    asm volatile("ldmatrix.sync.aligned.m8n8.x4.shared.b16 {%0,%1,%2,%3}, [%4];"
                 : "=r"(r[0]), "=r"(r[1]), "=r"(r[2]), "=r"(r[3]) : "r"(addr));
}
__device__ __forceinline__ void ldmatrix_x4_trans(uint32_t* r, uint32_t addr) {
    asm volatile("ldmatrix.sync.aligned.m8n8.x4.trans.shared.b16 {%0,%1,%2,%3}, [%4];"
                 : "=r"(r[0]), "=r"(r[1]), "=r"(r[2]), "=r"(r[3]) : "r"(addr));
}
__device__ __forceinline__ void mma_bf16(float* c, const uint32_t* a, uint32_t b0, uint32_t b1) {
    asm volatile("mma.sync.aligned.m16n8k16.row.col.f32.bf16.bf16.f32 "
                 "{%0,%1,%2,%3}, {%4,%5,%6,%7}, {%8,%9}, {%0,%1,%2,%3};"
                 : "+f"(c[0]), "+f"(c[1]), "+f"(c[2]), "+f"(c[3])
                 : "r"(a[0]), "r"(a[1]), "r"(a[2]), "r"(a[3]), "r"(b0), "r"(b1));
}
__device__ __forceinline__ uint32_t pack_bf2(float lo, float hi) {
    __nv_bfloat162 v = __floats2bfloat162_rn(lo, hi);  // x=lo (low half), y=hi
    return *reinterpret_cast<uint32_t*>(&v);
}
__device__ __forceinline__ void pack_store16(__nv_bfloat16* dst, float4 a, float4 b) {
    uint4 u;
    u.x = pack_bf2(a.x, a.y); u.y = pack_bf2(a.z, a.w);
    u.z = pack_bf2(b.x, b.y); u.w = pack_bf2(b.z, b.w);
    *reinterpret_cast<uint4*>(dst) = u;
}

__global__ void __launch_bounds__(256) gemm_sigmoid_mma_kernel(
        const float* __restrict__ x,
        const float* __restrict__ w,
        float* __restrict__ out) {
    __shared__ __nv_bfloat16 As[2][BM * A_STRIDE];
    __shared__ __nv_bfloat16 Bs[2][BK * B_STRIDE];

    const int tid  = threadIdx.x;
    const int lane = tid & 31;
    const int wid  = tid >> 5;
    const int wm   = wid >> 2;        // 0..1  (M direction, 32 rows each)
    const int wn   = wid & 3;         // 0..3  (N direction, 32 cols each)

    const int m0 = blockIdx.y * BM;
    const int n0 = blockIdx.x * BN;

    // ---- global load mapping ----
    const int arow = tid >> 2;            // 0..63
    const int ak   = (tid & 3) << 3;      // 0,8,16,24  (2x float4)
    const int brow = tid >> 3;            // 0..31
    const int bn   = (tid & 7) << 4;      // 0..112     (4x float4)

    const float* xg = x + (m0 + arow) * INDIM + ak;
    const float* wg = w + brow * OUTDIM + n0 + bn;

    // ---- register prefetch buffers ----
    float4 aR0, aR1, bR0, bR1, bR2, bR3;

    // ---- accumulators: 2 (mt) x 4 (nt) mma tiles x 4 regs ----
    float acc[2][4][4];
    #pragma unroll
    for (int i = 0; i < 2; ++i)
        #pragma unroll
        for (int j = 0; j < 4; ++j)
            #pragma unroll
            for (int k = 0; k < 4; ++k)
                acc[i][j][k] = 0.0f;

    // ---- per-lane ldmatrix offsets (byte offsets within a buffer) ----
    const int lr = lane & 15;
    const int lc = (lane >> 4) << 3;   // 0 or 8
    // A: mt in {0,1}, kstep s in {0,1}: row = wm*32 + mt*16 + lr, col = s*16 + lc
    uint32_t a_off[2][2];
    #pragma unroll
    for (int mt = 0; mt < 2; ++mt)
        #pragma unroll
        for (int s = 0; s < 2; ++s)
            a_off[mt][s] = ((wm * 32 + mt * 16 + lr) * A_STRIDE + s * 16 + lc) * 2;
    // B: pair p in {0,1} (covers ntiles 2p,2p+1), kstep s: row = s*16 + lr, col = wn*32 + p*16 + lc
    uint32_t b_off[2][2];
    #pragma unroll
    for (int p = 0; p < 2; ++p)
        #pragma unroll
        for (int s = 0; s < 2; ++s)
            b_off[p][s] = ((s * 16 + lr) * B_STRIDE + wn * 32 + p * 16 + lc) * 2;

    const uint32_t As_base = (uint32_t)__cvta_generic_to_shared(&As[0][0]);
    const uint32_t Bs_base = (uint32_t)__cvta_generic_to_shared(&Bs[0][0]);

    // ---- prologue: load tile 0 and commit to smem buf 0 ----
    aR0 = *(const float4*)(xg);
    aR1 = *(const float4*)(xg + 4);
    bR0 = *(const float4*)(wg);
    bR1 = *(const float4*)(wg + 4);
    bR2 = *(const float4*)(wg + 8);
    bR3 = *(const float4*)(wg + 12);
    pack_store16(&As[0][arow * A_STRIDE + ak], aR0, aR1);
    pack_store16(&Bs[0][brow * B_STRIDE + bn], bR0, bR1);
    pack_store16(&Bs[0][brow * B_STRIDE + bn + 8], bR2, bR3);
    __syncthreads();

    for (int it = 0; it < NITER; ++it) {
        const int buf = it & 1;

        // prefetch next k-chunk into registers (overlaps with mma below)
        if (it + 1 < NITER) {
            const int k1 = (it + 1) * BK;
            aR0 = *(const float4*)(xg + k1);
            aR1 = *(const float4*)(xg + k1 + 4);
            const float* wgk = wg + (size_t)k1 * OUTDIM;
            bR0 = *(const float4*)(wgk);
            bR1 = *(const float4*)(wgk + 4);
            bR2 = *(const float4*)(wgk + 8);
            bR3 = *(const float4*)(wgk + 12);
        }

        const uint32_t Ab = As_base + buf * A_BUF_BYTES;
        const uint32_t Bb = Bs_base + buf * B_BUF_BYTES;

        #pragma unroll
        for (int s = 0; s < 2; ++s) {
            uint32_t af[2][4], bf[2][4];
            ldmatrix_x4(af[0], Ab + a_off[0][s]);
            ldmatrix_x4(af[1], Ab + a_off[1][s]);
            ldmatrix_x4_trans(bf[0], Bb + b_off[0][s]);
            ldmatrix_x4_trans(bf[1], Bb + b_off[1][s]);
            #pragma unroll
            for (int mt = 0; mt < 2; ++mt) {
                mma_bf16(acc[mt][0], af[mt], bf[0][0], bf[0][1]);
                mma_bf16(acc[mt][1], af[mt], bf[0][2], bf[0][3]);
                mma_bf16(acc[mt][2], af[mt], bf[1][0], bf[1][1]);
                mma_bf16(acc[mt][3], af[mt], bf[1][2], bf[1][3]);
            }
        }

        if (it + 1 < NITER) {
            const int nbuf = 1 - buf;
            pack_store16(&As[nbuf][arow * A_STRIDE + ak], aR0, aR1);
            pack_store16(&Bs[nbuf][brow * B_STRIDE + bn], bR0, bR1);
            pack_store16(&Bs[nbuf][brow * B_STRIDE + bn + 8], bR2, bR3);
            __syncthreads();
        }
    }

    // ---- epilogue: bias mean + sigmoid ----
    const float inv = 1.0f / (float)INDIM;
    const int crow = lane >> 2;             // 0..7
    const int ccol = (lane & 3) << 1;       // 0,2,4,6

    #pragma unroll
    for (int nt = 0; nt < 4; ++nt) {
        const int col = n0 + wn * 32 + nt * 8 + ccol;
        float bs0 = 0.0f, bs1 = 0.0f;
        #pragma unroll
        for (int p = 0; p < NPART; ++p) {
            bs0 += g_bias_part[p][col];
            bs1 += g_bias_part[p][col + 1];
        }
        #pragma unroll
        for (int mt = 0; mt < 2; ++mt) {
            const int row0 = m0 + wm * 32 + mt * 16 + crow;
            float t0 = (acc[mt][nt][0] + bs0) * inv;
            float t1 = (acc[mt][nt][1] + bs1) * inv;
            float t2 = (acc[mt][nt][2] + bs0) * inv;
            float t3 = (acc[mt][nt][3] + bs1) * inv;
            float2 r0 = make_float2(1.0f / (1.0f + __expf(-t0)),
                                    1.0f / (1.0f + __expf(-t1)));
            float2 r1 = make_float2(1.0f / (1.0f + __expf(-t2)),
                                    1.0f / (1.0f + __expf(-t3)));
            *reinterpret_cast<float2*>(&out[row0 * OUTDIM + col])       = r0;
            *reinterpret_cast<float2*>(&out[(row0 + 8) * OUTDIM + col]) = r1;
        }
    }
}

// ---------------------------------------------------------------------------
extern "C" void kernel_launch(void* const* d_in, const int* in_sizes, int n_in,
                              void* d_out, int out_size) {
    const float* x    = (const float*)d_in[0];
    const float* wgt  = (const float*)d_in[1];
    const float* bias = (const float*)d_in[2];
    float* out        = (float*)d_out;
    (void)in_sizes; (void)n_in; (void)out_size;

    dim3 g1(OUTDIM / 256, NPART);
    bias_colsum_kernel<<<g1, 256>>>(bias);

    dim3 g2(OUTDIM / BN, BATCH / BM);   // (8, 4) = 32 blocks
    gemm_sigmoid_mma_kernel<<<g2, 256>>>(x, wgt, out);
}

// round 3
// speedup vs baseline: 2.2489x; 2.2468x over previous
#include <cuda_runtime.h>
#include <cuda_bf16.h>
#include <cstdint>

// out[b,o] = sigmoid( mean_i( x[b,i]*W[i,o] + bias[i,o] ) )
//          = sigmoid( (x@W + colsum(bias))[b,o] / 1024 )
// Split-K bf16 tensor-core GEMM (256 CTAs) + fused bias colsum CTAs, then a
// small reduce+sigmoid epilogue kernel.

#define BATCH   256
#define INDIM   1024
#define OUTDIM  1024

#define KSPLIT  4
#define KCHUNK  (INDIM / KSPLIT)   // 256
#define BK      32
#define NIT     (KCHUNK / BK)      // 8
#define BM      64
#define BN      64

#define A_STRIDE 40   // bf16 units: 80B rows -> conflict-free ldmatrix (80%128 pattern distinct)
#define B_STRIDE 72   // bf16 units: 144B rows (144%128==16)
#define A_BUF_BYTES (BM * A_STRIDE * 2)
#define B_BUF_BYTES (BK * B_STRIDE * 2)

// scratch (device globals: no allocation allowed)
__device__ float g_part[KSPLIT][BATCH * OUTDIM];   // 4 MB fp32 partials
__device__ float g_bias_part[KSPLIT][OUTDIM];      // per-k-slice bias colsums

__device__ __forceinline__ void ldmatrix_x4(uint32_t* r, uint32_t addr) {
    asm volatile("ldmatrix.sync.aligned.m8n8.x4.shared.b16 {%0,%1,%2,%3}, [%4];"
                 : "=r"(r[0]), "=r"(r[1]), "=r"(r[2]), "=r"(r[3]) : "r"(addr));
}
__device__ __forceinline__ void ldmatrix_x4_trans(uint32_t* r, uint32_t addr) {
    asm volatile("ldmatrix.sync.aligned.m8n8.x4.trans.shared.b16 {%0,%1,%2,%3}, [%4];"
                 : "=r"(r[0]), "=r"(r[1]), "=r"(r[2]), "=r"(r[3]) : "r"(addr));
}
__device__ __forceinline__ void mma_bf16(float* c, const uint32_t* a, uint32_t b0, uint32_t b1) {
    asm volatile("mma.sync.aligned.m16n8k16.row.col.f32.bf16.bf16.f32 "
                 "{%0,%1,%2,%3}, {%4,%5,%6,%7}, {%8,%9}, {%0,%1,%2,%3};"
                 : "+f"(c[0]), "+f"(c[1]), "+f"(c[2]), "+f"(c[3])
                 : "r"(a[0]), "r"(a[1]), "r"(a[2]), "r"(a[3]), "r"(b0), "r"(b1));
}
__device__ __forceinline__ uint32_t pack_bf2(float lo, float hi) {
    __nv_bfloat162 v = __floats2bfloat162_rn(lo, hi);
    return *reinterpret_cast<uint32_t*>(&v);
}
__device__ __forceinline__ void pack_store16(__nv_bfloat16* dst, float4 a, float4 b) {
    uint4 u;
    u.x = pack_bf2(a.x, a.y); u.y = pack_bf2(a.z, a.w);
    u.z = pack_bf2(b.x, b.y); u.w = pack_bf2(b.z, b.w);
    *reinterpret_cast<uint4*>(dst) = u;
}

// ---------------------------------------------------------------------------
// Kernel 1: split-K GEMM partials + bias colsum partials, one launch.
// grid = (16 n-tiles, 5, 4 k-slices); y<4 => GEMM m-tile, y==4 => bias block.
// 256 threads.
// ---------------------------------------------------------------------------
__global__ void __launch_bounds__(256) gemm_splitk_kernel(
        const float* __restrict__ x,
        const float* __restrict__ w,
        const float* __restrict__ bias) {
    __shared__ __nv_bfloat16 As[2][BM * A_STRIDE];
    __shared__ __nv_bfloat16 Bs[2][BK * B_STRIDE];
    __shared__ float red[4][BN];

    const int tid = threadIdx.x;
    const int n0  = blockIdx.x * BN;
    const int kz  = blockIdx.z;
    const int k0  = kz * KCHUNK;

    // ---------------- bias colsum blocks ----------------
    if (blockIdx.y == 4) {
        const int col = tid & 63;
        const int rg  = tid >> 6;            // 0..3, each covers 64 rows
        const float* bp = bias + (size_t)(k0 + rg * 64) * OUTDIM + n0 + col;
        float s = 0.0f;
        #pragma unroll 16
        for (int r = 0; r < 64; ++r)
            s += __ldg(bp + (size_t)r * OUTDIM);
        red[rg][col] = s;
        __syncthreads();
        if (tid < 64) {
            float t = red[0][tid] + red[1][tid] + red[2][tid] + red[3][tid];
            g_bias_part[kz][n0 + tid] = t;
        }
        return;
    }

    // ---------------- GEMM blocks ----------------
    const int m0   = blockIdx.y * BM;
    const int lane = tid & 31;
    const int wid  = tid >> 5;
    const int wm   = wid >> 2;   // 0..1 -> 32 rows
    const int wn   = wid & 3;    // 0..3 -> 16 cols

    // global load mapping: 8 floats A + 8 floats B per thread per iter
    const int arow = tid >> 2;           // 0..63
    const int ak   = (tid & 3) << 3;     // 0,8,16,24
    const int brow = tid >> 3;           // 0..31
    const int bno  = (tid & 7) << 3;     // 0..56

    const float* xg = x + (size_t)(m0 + arow) * INDIM + k0 + ak;
    const float* wg = w + (size_t)(k0 + brow) * OUTDIM + n0 + bno;

    float acc[2][2][4];
    #pragma unroll
    for (int i = 0; i < 2; ++i)
        #pragma unroll
        for (int j = 0; j < 2; ++j)
            #pragma unroll
            for (int c = 0; c < 4; ++c)
                acc[i][j][c] = 0.0f;

    const int lr = lane & 15;
    const int lc = (lane >> 4) << 3;
    uint32_t a_off[2][2], b_off[2];
    #pragma unroll
    for (int mt = 0; mt < 2; ++mt)
        #pragma unroll
        for (int s = 0; s < 2; ++s)
            a_off[mt][s] = ((wm * 32 + mt * 16 + lr) * A_STRIDE + s * 16 + lc) * 2;
    #pragma unroll
    for (int s = 0; s < 2; ++s)
        b_off[s] = ((s * 16 + lr) * B_STRIDE + wn * 16 + lc) * 2;

    const uint32_t As_base = (uint32_t)__cvta_generic_to_shared(&As[0][0]);
    const uint32_t Bs_base = (uint32_t)__cvta_generic_to_shared(&Bs[0][0]);

    // prologue
    float4 aR0 = *(const float4*)(xg);
    float4 aR1 = *(const float4*)(xg + 4);
    float4 bR0 = *(const float4*)(wg);
    float4 bR1 = *(const float4*)(wg + 4);
    pack_store16(&As[0][arow * A_STRIDE + ak], aR0, aR1);
    pack_store16(&Bs[0][brow * B_STRIDE + bno], bR0, bR1);
    __syncthreads();

    #pragma unroll
    for (int it = 0; it < NIT; ++it) {
        const int buf = it & 1;

        if (it + 1 < NIT) {
            const int k1 = (it + 1) * BK;
            aR0 = *(const float4*)(xg + k1);
            aR1 = *(const float4*)(xg + k1 + 4);
            const float* wgk = wg + (size_t)k1 * OUTDIM;
            bR0 = *(const float4*)(wgk);
            bR1 = *(const float4*)(wgk + 4);
        }

        const uint32_t Ab = As_base + buf * A_BUF_BYTES;
        const uint32_t Bb = Bs_base + buf * B_BUF_BYTES;

        #pragma unroll
        for (int s = 0; s < 2; ++s) {
            uint32_t af[2][4], bf[4];
            ldmatrix_x4(af[0], Ab + a_off[0][s]);
            ldmatrix_x4(af[1], Ab + a_off[1][s]);
            ldmatrix_x4_trans(bf, Bb + b_off[s]);
            #pragma unroll
            for (int mt = 0; mt < 2; ++mt) {
                mma_bf16(acc[mt][0], af[mt], bf[0], bf[1]);
                mma_bf16(acc[mt][1], af[mt], bf[2], bf[3]);
            }
        }

        if (it + 1 < NIT) {
            const int nbuf = (it + 1) & 1;
            pack_store16(&As[nbuf][arow * A_STRIDE + ak], aR0, aR1);
            pack_store16(&Bs[nbuf][brow * B_STRIDE + bno], bR0, bR1);
            __syncthreads();
        }
    }

    // write fp32 partials
    float* pg = g_part[kz];
    const int crow = lane >> 2;
    const int ccol = (lane & 3) << 1;
    #pragma unroll
    for (int nt = 0; nt < 2; ++nt) {
        const int col = n0 + wn * 16 + nt * 8 + ccol;
        #pragma unroll
        for (int mt = 0; mt < 2; ++mt) {
            const int row0 = m0 + wm * 32 + mt * 16 + crow;
            *reinterpret_cast<float2*>(&pg[(size_t)row0 * OUTDIM + col]) =
                make_float2(acc[mt][nt][0], acc[mt][nt][1]);
            *reinterpret_cast<float2*>(&pg[(size_t)(row0 + 8) * OUTDIM + col]) =
                make_float2(acc[mt][nt][2], acc[mt][nt][3]);
        }
    }
}

// ---------------------------------------------------------------------------
// Kernel 2: reduce partials + bias, mean, sigmoid. 256 blocks x 256 thr,
// one float4 per thread.
// ---------------------------------------------------------------------------
__global__ void __launch_bounds__(256) epilogue_kernel(float* __restrict__ out) {
    const int idx = (blockIdx.x * 256 + threadIdx.x) << 2;   // element index
    const int o   = idx & (OUTDIM - 1);

    float4 s = make_float4(0.f, 0.f, 0.f, 0.f);
    #pragma unroll
    for (int k = 0; k < KSPLIT; ++k) {
        float4 p = *reinterpret_cast<const float4*>(&g_part[k][idx]);
        s.x += p.x; s.y += p.y; s.z += p.z; s.w += p.w;
    }
    float b0 = 0.f, b1 = 0.f, b2 = 0.f, b3 = 0.f;
    #pragma unroll
    for (int k = 0; k < KSPLIT; ++k) {
        b0 += g_bias_part[k][o + 0];
        b1 += g_bias_part[k][o + 1];
        b2 += g_bias_part[k][o + 2];
        b3 += g_bias_part[k][o + 3];
    }
    const float inv = 1.0f / (float)INDIM;
    float4 r;
    r.x = 1.0f / (1.0f + __expf(-(s.x + b0) * inv));
    r.y = 1.0f / (1.0f + __expf(-(s.y + b1) * inv));
    r.z = 1.0f / (1.0f + __expf(-(s.z + b2) * inv));
    r.w = 1.0f / (1.0f + __expf(-(s.w + b3) * inv));
    *reinterpret_cast<float4*>(&out[idx]) = r;
}

// ---------------------------------------------------------------------------
extern "C" void kernel_launch(void* const* d_in, const int* in_sizes, int n_in,
                              void* d_out, int out_size) {
    const float* x    = (const float*)d_in[0];
    const float* wgt  = (const float*)d_in[1];
    const float* bias = (const float*)d_in[2];
    float* out        = (float*)d_out;
    (void)in_sizes; (void)n_in; (void)out_size;

    dim3 g1(OUTDIM / BN, BATCH / BM + 1, KSPLIT);   // (16, 5, 4) = 320 CTAs
    gemm_splitk_kernel<<<g1, 256>>>(x, wgt, bias);

    epilogue_kernel<<<BATCH * OUTDIM / 1024, 256>>>(out);
}